// round 16
// baseline (speedup 1.0000x reference)
#include <cuda_runtime.h>
#include <cuda_fp16.h>
#include <cstdint>
#include <mma.h>

// Problem constants
#define BB 8
#define NN 4096
#define DD 768
#define HH 64

// attn smem leading dim (halves): 72 -> bank = 4g+tig, conflict-free
#define LDH 72
#define TILEH (64 * LDH)

// proj smem tiles (halves)
#define PLDH 72
#define XBUF (64 * PLDH)
#define WBUF (3 * 64 * PLDH)

// Q prescale: 1/sqrt(64) * log2(e), folded so attn can use ex2 directly
#define QSCALE 0.18033688f

// Device scratch: fp16 projections. Q has QSCALE pre-folded. V stored transposed [b][d][n].
__device__ __half g_q[BB * NN * HH];
__device__ __half g_k[BB * NN * HH];
__device__ __half g_vT[BB * HH * NN];
__device__ __half g_whT[3 * HH * DD];

// ---------------------------------------------------------------------------
// helpers
// ---------------------------------------------------------------------------
__device__ __forceinline__ void cp_async16(void* smem_dst, const void* gmem_src) {
    unsigned s = (unsigned)__cvta_generic_to_shared(smem_dst);
    asm volatile("cp.async.cg.shared.global [%0], [%1], 16;\n" :: "r"(s), "l"(gmem_src));
}
__device__ __forceinline__ void cp_async_commit() {
    asm volatile("cp.async.commit_group;\n");
}
// f16 m16n8k16, f32 accumulate
__device__ __forceinline__ void mmaf16(float* d, const unsigned* a, const unsigned* b2,
                                       const float* c) {
    asm volatile(
        "mma.sync.aligned.m16n8k16.row.col.f32.f16.f16.f32 "
        "{%0,%1,%2,%3}, {%4,%5,%6,%7}, {%8,%9}, {%10,%11,%12,%13};\n"
        : "=f"(d[0]), "=f"(d[1]), "=f"(d[2]), "=f"(d[3])
        : "r"(a[0]), "r"(a[1]), "r"(a[2]), "r"(a[3]),
          "r"(b2[0]), "r"(b2[1]),
          "f"(c[0]), "f"(c[1]), "f"(c[2]), "f"(c[3]));
}
// f16 m16n8k16, f16 accumulate (S matrix)
__device__ __forceinline__ void mmaf16h(unsigned* d, const unsigned* a, const unsigned* b2,
                                        const unsigned* c) {
    asm volatile(
        "mma.sync.aligned.m16n8k16.row.col.f16.f16.f16.f16 "
        "{%0,%1}, {%2,%3,%4,%5}, {%6,%7}, {%8,%9};\n"
        : "=r"(d[0]), "=r"(d[1])
        : "r"(a[0]), "r"(a[1]), "r"(a[2]), "r"(a[3]),
          "r"(b2[0]), "r"(b2[1]),
          "r"(c[0]), "r"(c[1]));
}
__device__ __forceinline__ unsigned packh2(float lo, float hi) {
    __half2 h = __floats2half2_rn(lo, hi);
    return *(unsigned*)&h;
}
__device__ __forceinline__ unsigned ex2h2(unsigned x) {
    unsigned r;
    asm("ex2.approx.f16x2 %0, %1;" : "=r"(r) : "r"(x));
    return r;
}
__device__ __forceinline__ unsigned hadd2u(unsigned a, unsigned b) {
    __half2 r = __hadd2(*(__half2*)&a, *(__half2*)&b);
    return *(unsigned*)&r;
}
__device__ __forceinline__ void ldsm4(unsigned* r, unsigned saddr) {
    asm volatile("ldmatrix.sync.aligned.m8n8.x4.shared.b16 {%0,%1,%2,%3}, [%4];\n"
                 : "=r"(r[0]), "=r"(r[1]), "=r"(r[2]), "=r"(r[3]) : "r"(saddr));
}

// ---------------------------------------------------------------------------
// Kernel 0: W -> fp16 transposed [mm][n][k] (unchanged).
// ---------------------------------------------------------------------------
__global__ void wconv_kernel(const float* __restrict__ Wq,
                             const float* __restrict__ Wk,
                             const float* __restrict__ Wv)
{
    int id = blockIdx.x * 256 + threadIdx.x;
    int k = id % DD;
    int rem = id / DD;
    int n = rem & 63;
    int mm = rem >> 6;
    const float* W = (mm == 0) ? Wq : (mm == 1) ? Wk : Wv;
    g_whT[(size_t)mm * HH * DD + (size_t)n * DD + k] = __float2half_rn(W[(size_t)k * HH + n]);
}

// ---------------------------------------------------------------------------
// Kernel 1: fused Q/K/V projection, fp16 m16n8k16 (byte-identical to R12).
// ---------------------------------------------------------------------------
__global__ void __launch_bounds__(256, 2) proj_kernel(
    const float* __restrict__ x,
    const float* __restrict__ bq, const float* __restrict__ bk,
    const float* __restrict__ bv)
{
    extern __shared__ __half smh[];
    __half* xsm = smh;
    __half* wsm = smh + 2 * XBUF;

    const int tid  = threadIdx.x;
    const int warp = tid >> 5;
    const int lane = tid & 31;
    const int g    = lane >> 2;
    const int tig  = lane & 3;
    const int rg   = warp & 3;
    const int ch   = warp >> 2;
    const size_t row0 = (size_t)blockIdx.x * 64;

    const int lrow = tid >> 4;
    const int lc4  = tid & 15;

    float cacc[12][4];
#pragma unroll
    for (int j = 0; j < 12; j++)
#pragma unroll
        for (int i = 0; i < 4; i++) cacc[j][i] = 0.0f;

    uint2 ph[4];

#define LDX(kc)                                                                     \
    do {                                                                            \
        _Pragma("unroll")                                                           \
        for (int i = 0; i < 4; i++) {                                               \
            int row = lrow + i * 16;                                                \
            float4 v = *(const float4*)(x + (row0 + row) * DD + (kc) * 64 + lc4 * 4); \
            ph[i].x = packh2(v.x, v.y);                                             \
            ph[i].y = packh2(v.z, v.w);                                             \
        }                                                                           \
    } while (0)

#define STX(buf)                                                                    \
    do {                                                                            \
        _Pragma("unroll")                                                           \
        for (int i = 0; i < 4; i++) {                                               \
            int row = lrow + i * 16;                                                \
            *(uint2*)(xsm + (buf) * XBUF + row * PLDH + lc4 * 4) = ph[i];           \
        }                                                                           \
    } while (0)

#define LDW(kc, buf)                                                                \
    do {                                                                            \
        _Pragma("unroll")                                                           \
        for (int u = 0; u < 6; u++) {                                               \
            int t = tid + u * 256;                                                  \
            int mm = t >> 9, rem = t & 511, n = rem >> 3, c16 = rem & 7;            \
            cp_async16(wsm + (buf) * WBUF + mm * (64 * PLDH) + n * PLDH + c16 * 8,  \
                       g_whT + (size_t)mm * HH * DD + (size_t)n * DD + (kc) * 64 + c16 * 8); \
        }                                                                           \
        cp_async_commit();                                                          \
    } while (0)

    LDX(0);
    LDW(0, 0);
    STX(0);
    LDX(1);

    for (int kc = 0; kc < DD / 64; kc++) {
        const int cur = kc & 1;
        const int nxt = cur ^ 1;

        asm volatile("cp.async.wait_group 0;\n");
        __syncthreads();

        if (kc < DD / 64 - 1) {
            LDW(kc + 1, nxt);
            STX(nxt);
        }

        const __half* xs = xsm + cur * XBUF + rg * 16 * PLDH;
        unsigned a[4][4];
#pragma unroll
        for (int kk = 0; kk < 4; kk++) {
            a[kk][0] = *(const unsigned*)(xs + (size_t)g * PLDH + 16 * kk + 2 * tig);
            a[kk][1] = *(const unsigned*)(xs + (size_t)(g + 8) * PLDH + 16 * kk + 2 * tig);
            a[kk][2] = *(const unsigned*)(xs + (size_t)g * PLDH + 16 * kk + 2 * tig + 8);
            a[kk][3] = *(const unsigned*)(xs + (size_t)(g + 8) * PLDH + 16 * kk + 2 * tig + 8);
        }
#pragma unroll
        for (int j = 0; j < 12; j++) {
            int jj = ch * 12 + j;
            int mm = jj >> 3, nt = jj & 7;
            const __half* wt = wsm + cur * WBUF + mm * (64 * PLDH) + (nt * 8 + g) * PLDH;
#pragma unroll
            for (int kk = 0; kk < 4; kk++) {
                unsigned b2[2];
                b2[0] = *(const unsigned*)(wt + 16 * kk + 2 * tig);
                b2[1] = *(const unsigned*)(wt + 16 * kk + 2 * tig + 8);
                mmaf16(cacc[j], a[kk], b2, cacc[j]);
            }
        }

        if (kc < DD / 64 - 2) LDX(kc + 2);
    }

    const size_t rgg  = row0 + rg * 16 + g;
    const size_t rgg8 = rgg + 8;
#pragma unroll
    for (int j = 0; j < 12; j++) {
        int jj = ch * 12 + j;
        int mm = jj >> 3;
        int col = (jj & 7) * 8 + 2 * tig;
        if (mm == 0) {
            float b0 = bq[col], b1 = bq[col + 1];
            __half2 v0 = __floats2half2_rn(QSCALE * (cacc[j][0] + b0), QSCALE * (cacc[j][1] + b1));
            __half2 v8 = __floats2half2_rn(QSCALE * (cacc[j][2] + b0), QSCALE * (cacc[j][3] + b1));
            *(__half2*)(g_q + rgg * HH + col)  = v0;
            *(__half2*)(g_q + rgg8 * HH + col) = v8;
        } else if (mm == 1) {
            float b0 = bk[col], b1 = bk[col + 1];
            __half2 v0 = __floats2half2_rn(cacc[j][0] + b0, cacc[j][1] + b1);
            __half2 v8 = __floats2half2_rn(cacc[j][2] + b0, cacc[j][3] + b1);
            *(__half2*)(g_k + rgg * HH + col)  = v0;
            *(__half2*)(g_k + rgg8 * HH + col) = v8;
        } else {
            float b0 = bv[col], b1 = bv[col + 1];
            size_t bofs = (rgg >> 12) * (size_t)HH * NN;
            size_t n0 = rgg & 4095, n8 = rgg8 & 4095;
            g_vT[bofs + (size_t)col * NN + n0]       = __float2half_rn(cacc[j][0] + b0);
            g_vT[bofs + (size_t)(col + 1) * NN + n0] = __float2half_rn(cacc[j][1] + b1);
            g_vT[bofs + (size_t)col * NN + n8]       = __float2half_rn(cacc[j][2] + b0);
            g_vT[bofs + (size_t)(col + 1) * NN + n8] = __float2half_rn(cacc[j][3] + b1);
        }
    }
#undef LDX
#undef STX
#undef LDW
}

// ---------------------------------------------------------------------------
// Kernel 2: flash attention, block-pipelined S(kb) -> PV(kb-1) -> exp(kb),
// now with intra-phase ldmatrix software pipelining: kf ping-pong in S
// (ldsm for step t+1 issues before mma of step t) and vf0 ping-pong in PV.
// ---------------------------------------------------------------------------
__global__ void __launch_bounds__(256, 2) attn_kernel(float* __restrict__ out)
{
    extern __shared__ __half smh[];
    __half* s_k = smh;                  // [2][64][LDH]
    __half* s_v = smh + 2 * TILEH;      // [3][64][LDH]  (V^T: rows=d, cols=keys)

    const int tid  = threadIdx.x;
    const int warp = tid >> 5;
    const int lane = tid & 31;
    const int g    = lane >> 2;
    const int tig  = lane & 3;
    const int mat  = lane >> 3;
    const int r8   = lane & 7;
    const int b    = blockIdx.y;
    const int q0   = blockIdx.x * 128;

    const unsigned sk_u = (unsigned)__cvta_generic_to_shared(s_k);
    const unsigned sv_u = (unsigned)__cvta_generic_to_shared(s_v);

    // ---- persistent Q A-fragments (fp16, QSCALE pre-folded) ----
    const __half* qbase = g_q + (size_t)(b * NN + q0 + warp * 16) * HH;
    unsigned qa[4][4];
#pragma unroll
    for (int kk = 0; kk < 4; kk++) {
        qa[kk][0] = *(const unsigned*)(qbase + (size_t)g * HH + 16 * kk + 2 * tig);
        qa[kk][1] = *(const unsigned*)(qbase + (size_t)(g + 8) * HH + 16 * kk + 2 * tig);
        qa[kk][2] = *(const unsigned*)(qbase + (size_t)g * HH + 16 * kk + 2 * tig + 8);
        qa[kk][3] = *(const unsigned*)(qbase + (size_t)(g + 8) * HH + 16 * kk + 2 * tig + 8);
    }

    float oacc[8][4];
#pragma unroll
    for (int j = 0; j < 8; j++)
#pragma unroll
        for (int i = 0; i < 4; i++) oacc[j][i] = 0.0f;
    float lrow0 = 0.0f, lrow8 = 0.0f;
    unsigned paf[4][4];                 // P of previous block, lives across iters

    const __half* gk  = g_k + (size_t)b * NN * HH;
    const __half* gvT = g_vT + (size_t)b * HH * NN;

#define PRE(kb_, kbuf_, vstage_)                                                    \
    do {                                                                            \
        _Pragma("unroll")                                                           \
        for (int u = 0; u < 2; u++) {                                               \
            int id = tid + u * 256;                                                 \
            int row = id >> 3, c16 = id & 7;                                        \
            cp_async16(s_k + (kbuf_) * TILEH + row * LDH + c16 * 8,                 \
                       gk + (size_t)((kb_) * 64 + row) * HH + c16 * 8);             \
            cp_async16(s_v + (vstage_) * TILEH + row * LDH + c16 * 8,               \
                       gvT + (size_t)row * NN + (kb_) * 64 + c16 * 8);              \
        }                                                                           \
        cp_async_commit();                                                          \
    } while (0)

// K fragment address for step t (kk = t>>2, c2 = t&3)
#define KADDR(ka_, t_) \
    ((ka_) + ((unsigned)(((t_) & 3) * 16 * LDH + ((t_) >> 2) * 16) << 1))

// PV body: vf0 ping-pong across j; vf1 loaded inline (its latency is covered
// by the two mma on vf0cur).
#define PV(vs_)                                                                     \
    do {                                                                            \
        const unsigned va = sv_u + (unsigned)(vs_) * (TILEH * 2) +                  \
                            ((unsigned)(r8 * LDH + mat * 8) << 1);                  \
        unsigned vfA[4], vfB[4], vf1[4];                                            \
        ldsm4(vfA, va);                                                             \
        _Pragma("unroll")                                                           \
        for (int j = 0; j < 8; j++) {                                               \
            unsigned* v0c = (j & 1) ? vfB : vfA;                                    \
            unsigned* v0n = (j & 1) ? vfA : vfB;                                    \
            ldsm4(vf1, va + ((unsigned)(j * 8 * LDH + 32) << 1));                   \
            if (j < 7) ldsm4(v0n, va + ((unsigned)((j + 1) * 8 * LDH) << 1));       \
            mmaf16(oacc[j], paf[0], v0c + 0, oacc[j]);                              \
            mmaf16(oacc[j], paf[1], v0c + 2, oacc[j]);                              \
            mmaf16(oacc[j], paf[2], vf1 + 0, oacc[j]);                              \
            mmaf16(oacc[j], paf[3], vf1 + 2, oacc[j]);                              \
        }                                                                           \
    } while (0)

    PRE(0, 0, 0);

    int vs_cur = 0;                     // V stage of the current block

    for (int kb = 0; kb < NN / 64; kb++) {
        const int kcur = kb & 1;
        const int vs_nxt  = (vs_cur == 2) ? 0 : vs_cur + 1;
        const int vs_prev = (vs_cur == 0) ? 2 : vs_cur - 1;

        asm volatile("cp.async.wait_group 0;\n");
        __syncthreads();

        if (kb < NN / 64 - 1)
            PRE(kb + 1, kcur ^ 1, vs_nxt);

        // ---- S(kb): f16 accumulate, kf ping-pong (ldsm t+1 before mma t) ----
        const unsigned ka = sk_u + (unsigned)kcur * (TILEH * 2) +
            ((unsigned)((((mat >> 1) << 3) + r8) * LDH + ((mat & 1) << 3)) << 1);
        unsigned sd[8][2];
#pragma unroll
        for (int c = 0; c < 8; c++) { sd[c][0] = 0u; sd[c][1] = 0u; }

        {
            unsigned kfA[4], kfB[4];
            ldsm4(kfA, KADDR(ka, 0));
#pragma unroll
            for (int t = 0; t < 16; t++) {
                unsigned* cur = (t & 1) ? kfB : kfA;
                unsigned* nxt = (t & 1) ? kfA : kfB;
                if (t < 15) ldsm4(nxt, KADDR(ka, t + 1));
                const int kk = t >> 2, c2 = t & 3;
                mmaf16h(sd[2 * c2],     qa[kk], cur + 0, sd[2 * c2]);
                mmaf16h(sd[2 * c2 + 1], qa[kk], cur + 2, sd[2 * c2 + 1]);
            }
        }

        // ---- PV(kb-1): fills the S-chain latency; no deps on S(kb) ----
        if (kb > 0)
            PV(vs_prev);

        // ---- exp(kb): ex2 directly on f16 accumulators (layout == A frag) ----
#pragma unroll
        for (int cp = 0; cp < 4; cp++) {
            paf[cp][0] = ex2h2(sd[2 * cp][0]);
            paf[cp][1] = ex2h2(sd[2 * cp][1]);
            paf[cp][2] = ex2h2(sd[2 * cp + 1][0]);
            paf[cp][3] = ex2h2(sd[2 * cp + 1][1]);
        }
        // per-thread l partials (row g: even idx; row g+8: odd idx)
        {
            unsigned hg = hadd2u(hadd2u(paf[0][0], paf[0][2]), hadd2u(paf[1][0], paf[1][2]));
            unsigned h8 = hadd2u(hadd2u(paf[0][1], paf[0][3]), hadd2u(paf[1][1], paf[1][3]));
            hg = hadd2u(hg, hadd2u(hadd2u(paf[2][0], paf[2][2]), hadd2u(paf[3][0], paf[3][2])));
            h8 = hadd2u(h8, hadd2u(hadd2u(paf[2][1], paf[2][3]), hadd2u(paf[3][1], paf[3][3])));
            float2 fg = __half22float2(*(__half2*)&hg);
            float2 f8 = __half22float2(*(__half2*)&h8);
            lrow0 += fg.x + fg.y;
            lrow8 += f8.x + f8.y;
        }

        vs_cur = vs_nxt;
    }

    // ---- peeled PV for the last block ----
    {
        const int vs_last = (vs_cur == 0) ? 2 : vs_cur - 1;
        PV(vs_last);
    }

    // ---- l: reduce the 4-lane quad once ----
    lrow0 += __shfl_xor_sync(0xffffffffu, lrow0, 1);
    lrow0 += __shfl_xor_sync(0xffffffffu, lrow0, 2);
    lrow8 += __shfl_xor_sync(0xffffffffu, lrow8, 1);
    lrow8 += __shfl_xor_sync(0xffffffffu, lrow8, 2);
    float inv0 = 1.0f / lrow0;
    float inv8 = 1.0f / lrow8;

    float* orow0 = out + (size_t)(b * NN + q0 + warp * 16 + g) * HH;
    float* orow8 = out + (size_t)(b * NN + q0 + warp * 16 + g + 8) * HH;
#pragma unroll
    for (int j = 0; j < 8; j++) {
        float2 v0 = make_float2(oacc[j][0] * inv0, oacc[j][1] * inv0);
        float2 v8 = make_float2(oacc[j][2] * inv8, oacc[j][3] * inv8);
        *(float2*)(orow0 + j * 8 + 2 * tig) = v0;
        *(float2*)(orow8 + j * 8 + 2 * tig) = v8;
    }
#undef PRE
#undef PV
#undef KADDR
}

// ---------------------------------------------------------------------------
extern "C" void kernel_launch(void* const* d_in, const int* in_sizes, int n_in,
                              void* d_out, int out_size)
{
    const float* x  = (const float*)d_in[0];
    const float* Wq = (const float*)d_in[1];
    const float* bq = (const float*)d_in[2];
    const float* Wk = (const float*)d_in[3];
    const float* bk = (const float*)d_in[4];
    const float* Wv = (const float*)d_in[5];
    const float* bv = (const float*)d_in[6];
    float* out = (float*)d_out;

    const int smem_proj = (2 * XBUF + 2 * WBUF) * (int)sizeof(__half);   // 73728
    const int smem_attn = 5 * TILEH * (int)sizeof(__half);               // 46080

    (void)cudaFuncSetAttribute(proj_kernel, cudaFuncAttributeMaxDynamicSharedMemorySize, smem_proj);
    (void)cudaFuncSetAttribute(attn_kernel, cudaFuncAttributeMaxDynamicSharedMemorySize, smem_attn);

    wconv_kernel<<<(3 * HH * DD) / 256, 256>>>(Wq, Wk, Wv);
    proj_kernel<<<(BB * NN) / 64, 256, smem_proj>>>(x, bq, bk, bv);
    attn_kernel<<<dim3(NN / 128, BB), 256, smem_attn>>>(out);
}

// round 17
// speedup vs baseline: 1.0356x; 1.0356x over previous
#include <cuda_runtime.h>
#include <cuda_fp16.h>
#include <cstdint>
#include <mma.h>

// Problem constants
#define BB 8
#define NN 4096
#define DD 768
#define HH 64

// attn smem leading dim (halves): 72 -> bank = 4g+tig, conflict-free
#define LDH 72
#define TILEH (64 * LDH)

// proj smem tiles (halves)
#define PLDH 72
#define XBUF (64 * PLDH)
#define WBUF (3 * 64 * PLDH)

// Q prescale: 1/sqrt(64) * log2(e), folded so attn can use ex2 directly
#define QSCALE 0.18033688f

// Device scratch: fp16 projections. Q has QSCALE pre-folded. V stored transposed [b][d][n].
__device__ __half g_q[BB * NN * HH];
__device__ __half g_k[BB * NN * HH];
__device__ __half g_vT[BB * HH * NN];
__device__ __half g_whT[3 * HH * DD];

// ---------------------------------------------------------------------------
// helpers
// ---------------------------------------------------------------------------
__device__ __forceinline__ void cp_async16(void* smem_dst, const void* gmem_src) {
    unsigned s = (unsigned)__cvta_generic_to_shared(smem_dst);
    asm volatile("cp.async.cg.shared.global [%0], [%1], 16;\n" :: "r"(s), "l"(gmem_src));
}
__device__ __forceinline__ void cp_async_commit() {
    asm volatile("cp.async.commit_group;\n");
}
// f16 m16n8k16, f32 accumulate
__device__ __forceinline__ void mmaf16(float* d, const unsigned* a, const unsigned* b2,
                                       const float* c) {
    asm volatile(
        "mma.sync.aligned.m16n8k16.row.col.f32.f16.f16.f32 "
        "{%0,%1,%2,%3}, {%4,%5,%6,%7}, {%8,%9}, {%10,%11,%12,%13};\n"
        : "=f"(d[0]), "=f"(d[1]), "=f"(d[2]), "=f"(d[3])
        : "r"(a[0]), "r"(a[1]), "r"(a[2]), "r"(a[3]),
          "r"(b2[0]), "r"(b2[1]),
          "f"(c[0]), "f"(c[1]), "f"(c[2]), "f"(c[3]));
}
// f16 m16n8k16, f16 accumulate (S matrix)
__device__ __forceinline__ void mmaf16h(unsigned* d, const unsigned* a, const unsigned* b2,
                                        const unsigned* c) {
    asm volatile(
        "mma.sync.aligned.m16n8k16.row.col.f16.f16.f16.f16 "
        "{%0,%1}, {%2,%3,%4,%5}, {%6,%7}, {%8,%9};\n"
        : "=r"(d[0]), "=r"(d[1])
        : "r"(a[0]), "r"(a[1]), "r"(a[2]), "r"(a[3]),
          "r"(b2[0]), "r"(b2[1]),
          "r"(c[0]), "r"(c[1]));
}
__device__ __forceinline__ unsigned packh2(float lo, float hi) {
    __half2 h = __floats2half2_rn(lo, hi);
    return *(unsigned*)&h;
}
__device__ __forceinline__ unsigned ex2h2(unsigned x) {
    unsigned r;
    asm("ex2.approx.f16x2 %0, %1;" : "=r"(r) : "r"(x));
    return r;
}
__device__ __forceinline__ unsigned hadd2u(unsigned a, unsigned b) {
    __half2 r = __hadd2(*(__half2*)&a, *(__half2*)&b);
    return *(unsigned*)&r;
}
__device__ __forceinline__ void ldsm4(unsigned* r, unsigned saddr) {
    asm volatile("ldmatrix.sync.aligned.m8n8.x4.shared.b16 {%0,%1,%2,%3}, [%4];\n"
                 : "=r"(r[0]), "=r"(r[1]), "=r"(r[2]), "=r"(r[3]) : "r"(saddr));
}

// ---------------------------------------------------------------------------
// Kernel 0: W -> fp16 transposed [mm][n][k] (unchanged).
// ---------------------------------------------------------------------------
__global__ void wconv_kernel(const float* __restrict__ Wq,
                             const float* __restrict__ Wk,
                             const float* __restrict__ Wv)
{
    int id = blockIdx.x * 256 + threadIdx.x;
    int k = id % DD;
    int rem = id / DD;
    int n = rem & 63;
    int mm = rem >> 6;
    const float* W = (mm == 0) ? Wq : (mm == 1) ? Wk : Wv;
    g_whT[(size_t)mm * HH * DD + (size_t)n * DD + k] = __float2half_rn(W[(size_t)k * HH + n]);
}

// ---------------------------------------------------------------------------
// Kernel 1: fused Q/K/V projection, fp16 m16n8k16. Fragment loads now via
// ldmatrix.x4: 4 for A (per kk) + 24 for W (per j-pair x kk), replacing
// 112 scalar LDS per chunk with 28 LDSM. Bit-identical fragments.
// ---------------------------------------------------------------------------
__global__ void __launch_bounds__(256, 2) proj_kernel(
    const float* __restrict__ x,
    const float* __restrict__ bq, const float* __restrict__ bk,
    const float* __restrict__ bv)
{
    extern __shared__ __half smh[];
    __half* xsm = smh;
    __half* wsm = smh + 2 * XBUF;

    const int tid  = threadIdx.x;
    const int warp = tid >> 5;
    const int lane = tid & 31;
    const int g    = lane >> 2;
    const int tig  = lane & 3;
    const int mat  = lane >> 3;
    const int r8   = lane & 7;
    const int rg   = warp & 3;
    const int ch   = warp >> 2;
    const size_t row0 = (size_t)blockIdx.x * 64;

    const int lrow = tid >> 4;
    const int lc4  = tid & 15;

    const unsigned xsm_u = (unsigned)__cvta_generic_to_shared(xsm);
    const unsigned wsm_u = (unsigned)__cvta_generic_to_shared(wsm);

    // A-fragment ldsm base offset: matrices {rows lo k-lo, rows hi k-lo,
    // rows lo k-hi, rows hi k-hi} of the warp's 16-row slice.
    const unsigned xa_off =
        ((unsigned)((rg * 16 + ((mat & 1) << 3) + r8) * PLDH + ((mat >> 1) << 3)) << 1);

    // W-fragment ldsm base offsets for 6 j-pairs: matrices {j k-lo, j k-hi,
    // j+1 k-lo, j+1 k-hi}. Pairs are even-aligned so they never cross mm blocks.
    unsigned wb_off[6];
#pragma unroll
    for (int p = 0; p < 6; p++) {
        int jj  = ch * 12 + 2 * p;
        int mmw = jj >> 3, ntn = jj & 7;
        int nrow = mmw * 64 + ntn * 8 + ((mat >> 1) << 3) + r8;
        wb_off[p] = ((unsigned)(nrow * PLDH + ((mat & 1) << 3)) << 1);
    }

    float cacc[12][4];
#pragma unroll
    for (int j = 0; j < 12; j++)
#pragma unroll
        for (int i = 0; i < 4; i++) cacc[j][i] = 0.0f;

    uint2 ph[4];

#define LDX(kc)                                                                     \
    do {                                                                            \
        _Pragma("unroll")                                                           \
        for (int i = 0; i < 4; i++) {                                               \
            int row = lrow + i * 16;                                                \
            float4 v = *(const float4*)(x + (row0 + row) * DD + (kc) * 64 + lc4 * 4); \
            ph[i].x = packh2(v.x, v.y);                                             \
            ph[i].y = packh2(v.z, v.w);                                             \
        }                                                                           \
    } while (0)

#define STX(buf)                                                                    \
    do {                                                                            \
        _Pragma("unroll")                                                           \
        for (int i = 0; i < 4; i++) {                                               \
            int row = lrow + i * 16;                                                \
            *(uint2*)(xsm + (buf) * XBUF + row * PLDH + lc4 * 4) = ph[i];           \
        }                                                                           \
    } while (0)

#define LDW(kc, buf)                                                                \
    do {                                                                            \
        _Pragma("unroll")                                                           \
        for (int u = 0; u < 6; u++) {                                               \
            int t = tid + u * 256;                                                  \
            int mm = t >> 9, rem = t & 511, n = rem >> 3, c16 = rem & 7;            \
            cp_async16(wsm + (buf) * WBUF + mm * (64 * PLDH) + n * PLDH + c16 * 8,  \
                       g_whT + (size_t)mm * HH * DD + (size_t)n * DD + (kc) * 64 + c16 * 8); \
        }                                                                           \
        cp_async_commit();                                                          \
    } while (0)

    LDX(0);
    LDW(0, 0);
    STX(0);
    LDX(1);

    for (int kc = 0; kc < DD / 64; kc++) {
        const int cur = kc & 1;
        const int nxt = cur ^ 1;

        asm volatile("cp.async.wait_group 0;\n");
        __syncthreads();

        if (kc < DD / 64 - 1) {
            LDW(kc + 1, nxt);
            STX(nxt);
        }

        // ---- A fragments: one ldsm4 per kk ----
        const unsigned xabase = xsm_u + (unsigned)cur * (XBUF * 2) + xa_off;
        unsigned a[4][4];
#pragma unroll
        for (int kk = 0; kk < 4; kk++)
            ldsm4(a[kk], xabase + kk * 32);

        // ---- W fragments: one ldsm4 per (j-pair, kk) -> 2 mma each ----
        const unsigned wbase = wsm_u + (unsigned)cur * (WBUF * 2);
#pragma unroll
        for (int p = 0; p < 6; p++) {
#pragma unroll
            for (int kk = 0; kk < 4; kk++) {
                unsigned wf[4];
                ldsm4(wf, wbase + wb_off[p] + kk * 32);
                mmaf16(cacc[2 * p],     a[kk], wf + 0, cacc[2 * p]);
                mmaf16(cacc[2 * p + 1], a[kk], wf + 2, cacc[2 * p + 1]);
            }
        }

        if (kc < DD / 64 - 2) LDX(kc + 2);
    }

    const size_t rgg  = row0 + rg * 16 + g;
    const size_t rgg8 = rgg + 8;
#pragma unroll
    for (int j = 0; j < 12; j++) {
        int jj = ch * 12 + j;
        int mm = jj >> 3;
        int col = (jj & 7) * 8 + 2 * tig;
        if (mm == 0) {
            float b0 = bq[col], b1 = bq[col + 1];
            __half2 v0 = __floats2half2_rn(QSCALE * (cacc[j][0] + b0), QSCALE * (cacc[j][1] + b1));
            __half2 v8 = __floats2half2_rn(QSCALE * (cacc[j][2] + b0), QSCALE * (cacc[j][3] + b1));
            *(__half2*)(g_q + rgg * HH + col)  = v0;
            *(__half2*)(g_q + rgg8 * HH + col) = v8;
        } else if (mm == 1) {
            float b0 = bk[col], b1 = bk[col + 1];
            __half2 v0 = __floats2half2_rn(cacc[j][0] + b0, cacc[j][1] + b1);
            __half2 v8 = __floats2half2_rn(cacc[j][2] + b0, cacc[j][3] + b1);
            *(__half2*)(g_k + rgg * HH + col)  = v0;
            *(__half2*)(g_k + rgg8 * HH + col) = v8;
        } else {
            float b0 = bv[col], b1 = bv[col + 1];
            size_t bofs = (rgg >> 12) * (size_t)HH * NN;
            size_t n0 = rgg & 4095, n8 = rgg8 & 4095;
            g_vT[bofs + (size_t)col * NN + n0]       = __float2half_rn(cacc[j][0] + b0);
            g_vT[bofs + (size_t)(col + 1) * NN + n0] = __float2half_rn(cacc[j][1] + b1);
            g_vT[bofs + (size_t)col * NN + n8]       = __float2half_rn(cacc[j][2] + b0);
            g_vT[bofs + (size_t)(col + 1) * NN + n8] = __float2half_rn(cacc[j][3] + b1);
        }
    }
#undef LDX
#undef STX
#undef LDW
}

// ---------------------------------------------------------------------------
// Kernel 2: flash attention (byte-identical to R16 — at the legacy HMMA
// ceiling; S(kb) -> PV(kb-1) -> exp(kb) pipeline, f16-accum S, ex2.f16x2,
// per-thread l, ldsm ping-pong).
// ---------------------------------------------------------------------------
__global__ void __launch_bounds__(256, 2) attn_kernel(float* __restrict__ out)
{
    extern __shared__ __half smh[];
    __half* s_k = smh;                  // [2][64][LDH]
    __half* s_v = smh + 2 * TILEH;      // [3][64][LDH]  (V^T: rows=d, cols=keys)

    const int tid  = threadIdx.x;
    const int warp = tid >> 5;
    const int lane = tid & 31;
    const int g    = lane >> 2;
    const int tig  = lane & 3;
    const int mat  = lane >> 3;
    const int r8   = lane & 7;
    const int b    = blockIdx.y;
    const int q0   = blockIdx.x * 128;

    const unsigned sk_u = (unsigned)__cvta_generic_to_shared(s_k);
    const unsigned sv_u = (unsigned)__cvta_generic_to_shared(s_v);

    const __half* qbase = g_q + (size_t)(b * NN + q0 + warp * 16) * HH;
    unsigned qa[4][4];
#pragma unroll
    for (int kk = 0; kk < 4; kk++) {
        qa[kk][0] = *(const unsigned*)(qbase + (size_t)g * HH + 16 * kk + 2 * tig);
        qa[kk][1] = *(const unsigned*)(qbase + (size_t)(g + 8) * HH + 16 * kk + 2 * tig);
        qa[kk][2] = *(const unsigned*)(qbase + (size_t)g * HH + 16 * kk + 2 * tig + 8);
        qa[kk][3] = *(const unsigned*)(qbase + (size_t)(g + 8) * HH + 16 * kk + 2 * tig + 8);
    }

    float oacc[8][4];
#pragma unroll
    for (int j = 0; j < 8; j++)
#pragma unroll
        for (int i = 0; i < 4; i++) oacc[j][i] = 0.0f;
    float lrow0 = 0.0f, lrow8 = 0.0f;
    unsigned paf[4][4];

    const __half* gk  = g_k + (size_t)b * NN * HH;
    const __half* gvT = g_vT + (size_t)b * HH * NN;

#define PRE(kb_, kbuf_, vstage_)                                                    \
    do {                                                                            \
        _Pragma("unroll")                                                           \
        for (int u = 0; u < 2; u++) {                                               \
            int id = tid + u * 256;                                                 \
            int row = id >> 3, c16 = id & 7;                                        \
            cp_async16(s_k + (kbuf_) * TILEH + row * LDH + c16 * 8,                 \
                       gk + (size_t)((kb_) * 64 + row) * HH + c16 * 8);             \
            cp_async16(s_v + (vstage_) * TILEH + row * LDH + c16 * 8,               \
                       gvT + (size_t)row * NN + (kb_) * 64 + c16 * 8);              \
        }                                                                           \
        cp_async_commit();                                                          \
    } while (0)

#define KADDR(ka_, t_) \
    ((ka_) + ((unsigned)(((t_) & 3) * 16 * LDH + ((t_) >> 2) * 16) << 1))

#define PV(vs_)                                                                     \
    do {                                                                            \
        const unsigned va = sv_u + (unsigned)(vs_) * (TILEH * 2) +                  \
                            ((unsigned)(r8 * LDH + mat * 8) << 1);                  \
        unsigned vfA[4], vfB[4], vf1[4];                                            \
        ldsm4(vfA, va);                                                             \
        _Pragma("unroll")                                                           \
        for (int j = 0; j < 8; j++) {                                               \
            unsigned* v0c = (j & 1) ? vfB : vfA;                                    \
            unsigned* v0n = (j & 1) ? vfA : vfB;                                    \
            ldsm4(vf1, va + ((unsigned)(j * 8 * LDH + 32) << 1));                   \
            if (j < 7) ldsm4(v0n, va + ((unsigned)((j + 1) * 8 * LDH) << 1));       \
            mmaf16(oacc[j], paf[0], v0c + 0, oacc[j]);                              \
            mmaf16(oacc[j], paf[1], v0c + 2, oacc[j]);                              \
            mmaf16(oacc[j], paf[2], vf1 + 0, oacc[j]);                              \
            mmaf16(oacc[j], paf[3], vf1 + 2, oacc[j]);                              \
        }                                                                           \
    } while (0)

    PRE(0, 0, 0);

    int vs_cur = 0;

    for (int kb = 0; kb < NN / 64; kb++) {
        const int kcur = kb & 1;
        const int vs_nxt  = (vs_cur == 2) ? 0 : vs_cur + 1;
        const int vs_prev = (vs_cur == 0) ? 2 : vs_cur - 1;

        asm volatile("cp.async.wait_group 0;\n");
        __syncthreads();

        if (kb < NN / 64 - 1)
            PRE(kb + 1, kcur ^ 1, vs_nxt);

        const unsigned ka = sk_u + (unsigned)kcur * (TILEH * 2) +
            ((unsigned)((((mat >> 1) << 3) + r8) * LDH + ((mat & 1) << 3)) << 1);
        unsigned sd[8][2];
#pragma unroll
        for (int c = 0; c < 8; c++) { sd[c][0] = 0u; sd[c][1] = 0u; }

        {
            unsigned kfA[4], kfB[4];
            ldsm4(kfA, KADDR(ka, 0));
#pragma unroll
            for (int t = 0; t < 16; t++) {
                unsigned* cur = (t & 1) ? kfB : kfA;
                unsigned* nxt = (t & 1) ? kfA : kfB;
                if (t < 15) ldsm4(nxt, KADDR(ka, t + 1));
                const int kk = t >> 2, c2 = t & 3;
                mmaf16h(sd[2 * c2],     qa[kk], cur + 0, sd[2 * c2]);
                mmaf16h(sd[2 * c2 + 1], qa[kk], cur + 2, sd[2 * c2 + 1]);
            }
        }

        if (kb > 0)
            PV(vs_prev);

#pragma unroll
        for (int cp = 0; cp < 4; cp++) {
            paf[cp][0] = ex2h2(sd[2 * cp][0]);
            paf[cp][1] = ex2h2(sd[2 * cp][1]);
            paf[cp][2] = ex2h2(sd[2 * cp + 1][0]);
            paf[cp][3] = ex2h2(sd[2 * cp + 1][1]);
        }
        {
            unsigned hg = hadd2u(hadd2u(paf[0][0], paf[0][2]), hadd2u(paf[1][0], paf[1][2]));
            unsigned h8 = hadd2u(hadd2u(paf[0][1], paf[0][3]), hadd2u(paf[1][1], paf[1][3]));
            hg = hadd2u(hg, hadd2u(hadd2u(paf[2][0], paf[2][2]), hadd2u(paf[3][0], paf[3][2])));
            h8 = hadd2u(h8, hadd2u(hadd2u(paf[2][1], paf[2][3]), hadd2u(paf[3][1], paf[3][3])));
            float2 fg = __half22float2(*(__half2*)&hg);
            float2 f8 = __half22float2(*(__half2*)&h8);
            lrow0 += fg.x + fg.y;
            lrow8 += f8.x + f8.y;
        }

        vs_cur = vs_nxt;
    }

    {
        const int vs_last = (vs_cur == 0) ? 2 : vs_cur - 1;
        PV(vs_last);
    }

    lrow0 += __shfl_xor_sync(0xffffffffu, lrow0, 1);
    lrow0 += __shfl_xor_sync(0xffffffffu, lrow0, 2);
    lrow8 += __shfl_xor_sync(0xffffffffu, lrow8, 1);
    lrow8 += __shfl_xor_sync(0xffffffffu, lrow8, 2);
    float inv0 = 1.0f / lrow0;
    float inv8 = 1.0f / lrow8;

    float* orow0 = out + (size_t)(b * NN + q0 + warp * 16 + g) * HH;
    float* orow8 = out + (size_t)(b * NN + q0 + warp * 16 + g + 8) * HH;
#pragma unroll
    for (int j = 0; j < 8; j++) {
        float2 v0 = make_float2(oacc[j][0] * inv0, oacc[j][1] * inv0);
        float2 v8 = make_float2(oacc[j][2] * inv8, oacc[j][3] * inv8);
        *(float2*)(orow0 + j * 8 + 2 * tig) = v0;
        *(float2*)(orow8 + j * 8 + 2 * tig) = v8;
    }
#undef PRE
#undef PV
#undef KADDR
}

// ---------------------------------------------------------------------------
extern "C" void kernel_launch(void* const* d_in, const int* in_sizes, int n_in,
                              void* d_out, int out_size)
{
    const float* x  = (const float*)d_in[0];
    const float* Wq = (const float*)d_in[1];
    const float* bq = (const float*)d_in[2];
    const float* Wk = (const float*)d_in[3];
    const float* bk = (const float*)d_in[4];
    const float* Wv = (const float*)d_in[5];
    const float* bv = (const float*)d_in[6];
    float* out = (float*)d_out;

    const int smem_proj = (2 * XBUF + 2 * WBUF) * (int)sizeof(__half);   // 73728
    const int smem_attn = 5 * TILEH * (int)sizeof(__half);               // 46080

    (void)cudaFuncSetAttribute(proj_kernel, cudaFuncAttributeMaxDynamicSharedMemorySize, smem_proj);
    (void)cudaFuncSetAttribute(attn_kernel, cudaFuncAttributeMaxDynamicSharedMemorySize, smem_attn);

    wconv_kernel<<<(3 * HH * DD) / 256, 256>>>(Wq, Wk, Wv);
    proj_kernel<<<(BB * NN) / 64, 256, smem_proj>>>(x, bq, bk, bv);
    attn_kernel<<<dim3(NN / 128, BB), 256, smem_attn>>>(out);
}